// round 3
// baseline (speedup 1.0000x reference)
#include <cuda_runtime.h>
#include <cstdint>

// ---------------------------------------------------------------------------
// Problem constants
// ---------------------------------------------------------------------------
#define DIMX 16
#define HEADS 4
#define M_STEPS 8
#define RMAX 64
#define P_MAX 524288

// fold inv_sqrt(HD)=0.5 and log2(e) into q so the hot loop is dot + EX2 only
#define C_SCALE (0.5f * 1.4426950408889634f)

// ---------------------------------------------------------------------------
// Scratch (device globals -- no allocations allowed)
// g_kev layout: per tile of 32 positions, 16 float4 per position, transposed:
//   g_kev[tile*512 + j*32 + lane] = float4 j of position (tile*32+lane)
//   j 0..7  = KE (k + rel), interleaved re/im, heads contiguous (8 floats/head)
//   j 8..15 = V
// ---------------------------------------------------------------------------
__device__ float4 g_kev[(size_t)P_MAX * 16];      // 128 MB
__device__ float  g_qs[32];                        // scaled q for current step
__device__ float  g_z[32];                         // current z state (interleaved)
__device__ float  g_partials[1024 * 36];           // per-block partials

// ---------------------------------------------------------------------------
// Precompute: KE[p] = Wk @ x + bk + rel_table[idx(p)],  V[p] = Wv @ x + bv
// Positions in [P, PAD) get zero-filled slots (masked in step_kernel).
// ---------------------------------------------------------------------------
__global__ __launch_bounds__(128) void precompute_kernel(
    const float* __restrict__ z_past,
    const float* __restrict__ Wk, const float* __restrict__ bk,
    const float* __restrict__ Wv, const float* __restrict__ bv,
    const float* __restrict__ rel, const int* __restrict__ posp,
    int P, int PAD)
{
    __shared__ float sWk[1024], sWv[1024];
    __shared__ float sbk[32], sbv[32];
    __shared__ float srel[129 * 32];
    __shared__ float sx[128 * 33];    // padded to kill bank conflicts

    for (int i = threadIdx.x; i < 1024; i += 128) { sWk[i] = Wk[i]; sWv[i] = Wv[i]; }
    for (int i = threadIdx.x; i < 129 * 32; i += 128) srel[i] = rel[i];
    if (threadIdx.x < 32) { sbk[threadIdx.x] = bk[threadIdx.x]; sbv[threadIdx.x] = bv[threadIdx.x]; }

    int base = blockIdx.x * 128;
    int navail = P - base;
    if (navail > 128) navail = 128;
    if (navail < 0) navail = 0;
    for (int i = threadIdx.x; i < navail * 32; i += 128) {
        int p = i >> 5, j = i & 31;
        sx[p * 33 + j] = z_past[(size_t)base * 32 + i];
    }
    __syncthreads();

    int p = base + threadIdx.x;
    if (p >= PAD) return;

    int tile = p >> 5, lane = p & 31;
    float4* out = g_kev + (size_t)tile * 512 + lane;

    if (p >= P) {
        #pragma unroll
        for (int j = 0; j < 16; j++)
            out[j * 32] = make_float4(0.f, 0.f, 0.f, 0.f);
        return;
    }

    float x[32];
    #pragma unroll
    for (int j = 0; j < 32; j++) x[j] = sx[threadIdx.x * 33 + j];

    // robust pos decode: accept int32/int64-low-word, float-encoded, or missing
    int pos = P;
    if (posp) {
        int v = *posp;
        if (v > 0 && v < (1 << 28)) {
            pos = v;
        } else {
            float fv = __int_as_float(v);
            if (fv > 0.f && fv < 2.68e8f) pos = (int)fv;
        }
    }
    int idx = p + (pos - P) + RMAX;
    idx = min(max(idx, 0), 2 * RMAX);

    float ke[32], v[32];
    #pragma unroll 4
    for (int i = 0; i < 32; i++) {
        float ak = sbk[i], av = sbv[i];
        #pragma unroll
        for (int j = 0; j < 32; j++) {
            ak += sWk[i * 32 + j] * x[j];
            av += sWv[i * 32 + j] * x[j];
        }
        ke[i] = ak + srel[idx * 32 + i];
        v[i]  = av;
    }

    #pragma unroll
    for (int j = 0; j < 8; j++)
        out[j * 32] = make_float4(ke[4*j], ke[4*j+1], ke[4*j+2], ke[4*j+3]);
    #pragma unroll
    for (int j = 0; j < 8; j++)
        out[(8 + j) * 32] = make_float4(v[4*j], v[4*j+1], v[4*j+2], v[4*j+3]);
}

// ---------------------------------------------------------------------------
// Init: z = candidate (interleaved [16,2] == flat 32), q0 = Wq z + bq
// ---------------------------------------------------------------------------
__global__ void init_kernel(const float* __restrict__ cand,
                            const float* __restrict__ Wq,
                            const float* __restrict__ bq)
{
    __shared__ float sz[32];
    int i = threadIdx.x;   // 32 threads
    sz[i] = cand[i];
    __syncwarp();
    float q = bq[i];
    #pragma unroll
    for (int j = 0; j < 32; j++) q += Wq[i * 32 + j] * sz[j];
    g_z[i]  = sz[i];
    g_qs[i] = q * C_SCALE;
}

// ---------------------------------------------------------------------------
// Main streaming pass: per position, 4 scores -> exp2 -> weighted V accumulate.
// No max-subtraction (scores bounded ~|11| in exp2 domain, fp32 is fine).
// ---------------------------------------------------------------------------
__global__ __launch_bounds__(256, 2) void step_kernel(int ntiles, int P)
{
    __shared__ float sq[32];
    if (threadIdx.x < 32) sq[threadIdx.x] = g_qs[threadIdx.x];
    __syncthreads();

    float4 q[8];
    #pragma unroll
    for (int j = 0; j < 8; j++)
        q[j] = make_float4(sq[4*j], sq[4*j+1], sq[4*j+2], sq[4*j+3]);

    float4 acc[8];
    #pragma unroll
    for (int j = 0; j < 8; j++) acc[j] = make_float4(0.f, 0.f, 0.f, 0.f);
    float l[4] = {0.f, 0.f, 0.f, 0.f};

    int lane = threadIdx.x & 31;
    int gw   = (blockIdx.x * blockDim.x + threadIdx.x) >> 5;
    int nw   = (gridDim.x * blockDim.x) >> 5;

    for (int t = gw; t < ntiles; t += nw) {
        const float4* b = g_kev + (size_t)t * 512 + lane;
        float mask = (t * 32 + lane < P) ? 1.f : 0.f;
        float4 ke[8];
        #pragma unroll
        for (int j = 0; j < 8; j++) ke[j] = __ldg(b + j * 32);

        float s[4], w[4];
        #pragma unroll
        for (int h = 0; h < 4; h++) {
            float4 a = ke[2*h], c = ke[2*h+1];
            float4 qa = q[2*h], qb = q[2*h+1];
            s[h] = a.x*qa.x + a.y*qa.y + a.z*qa.z + a.w*qa.w
                 + c.x*qb.x + c.y*qb.y + c.z*qb.z + c.w*qb.w;
        }
        #pragma unroll
        for (int h = 0; h < 4; h++) {
            asm("ex2.approx.ftz.f32 %0, %1;" : "=f"(w[h]) : "f"(s[h]));
            w[h] *= mask;
            l[h] += w[h];
        }
        #pragma unroll
        for (int j = 0; j < 8; j++) {
            float4 v = __ldg(b + (8 + j) * 32);
            float ww = w[j >> 1];
            acc[j].x += ww * v.x; acc[j].y += ww * v.y;
            acc[j].z += ww * v.z; acc[j].w += ww * v.w;
        }
    }

    float vals[36];
    #pragma unroll
    for (int j = 0; j < 8; j++) {
        vals[4*j+0] = acc[j].x; vals[4*j+1] = acc[j].y;
        vals[4*j+2] = acc[j].z; vals[4*j+3] = acc[j].w;
    }
    #pragma unroll
    for (int h = 0; h < 4; h++) vals[32 + h] = l[h];

    #pragma unroll
    for (int off = 16; off; off >>= 1) {
        #pragma unroll
        for (int k = 0; k < 36; k++)
            vals[k] += __shfl_xor_sync(0xffffffffu, vals[k], off);
    }

    __shared__ float sred[8][36];
    int warp = threadIdx.x >> 5;
    if (lane == 0) {
        #pragma unroll
        for (int k = 0; k < 36; k++) sred[warp][k] = vals[k];
    }
    __syncthreads();
    if (threadIdx.x < 36) {
        float ssum = 0.f;
        int nwarp = blockDim.x >> 5;
        for (int wb = 0; wb < nwarp; wb++) ssum += sred[wb][threadIdx.x];
        g_partials[blockIdx.x * 36 + threadIdx.x] = ssum;
    }
}

// ---------------------------------------------------------------------------
// Finalize: merge partials -> out -> Wo GEMV -> z update -> mish -> LN -> next q
// Output convention disambiguated by out_elems:
//   16 -> real parts only (complex result coerced to float32 keeps Re)
//   32 -> interleaved [16,2] (also matches complex64 memory layout)
// ---------------------------------------------------------------------------
__global__ __launch_bounds__(128) void finalize_kernel(
    const float* __restrict__ Wo, const float* __restrict__ bo,
    const float* __restrict__ Wq, const float* __restrict__ bq,
    const float* __restrict__ coupling, const float* __restrict__ nscale,
    int m, int nblocks, float* __restrict__ out_final, int out_elems)
{
    __shared__ float red[36];
    __shared__ float sout[32];
    __shared__ float sz[32];
    int tid = threadIdx.x;

    if (tid < 36) {
        float s = 0.f;
        for (int b = 0; b < nblocks; b++) s += g_partials[b * 36 + tid];
        red[tid] = s;
    }
    __syncthreads();

    if (tid < 32) {
        sout[tid] = red[tid] / red[32 + (tid >> 3)];
    }
    __syncthreads();

    if (tid < 32) {
        float mod = bo[tid];
        #pragma unroll
        for (int j = 0; j < 32; j++) mod += Wo[tid * 32 + j] * sout[j];
        float zz = g_z[tid] + coupling[m] * mod;

        // mish(x) = x * tanh(softplus(x)), elementwise on re & im parts
        float sp = (zz > 20.f) ? zz : log1pf(expf(zz));
        float mm = zz * tanhf(sp);

        // LayerNorm separately over even (real) and odd (imag) lanes
        float s1 = mm, s2 = mm * mm;
        #pragma unroll
        for (int off = 2; off < 32; off <<= 1) {
            s1 += __shfl_xor_sync(0xffffffffu, s1, off);
            s2 += __shfl_xor_sync(0xffffffffu, s2, off);
        }
        float mu  = s1 * (1.f / 16.f);
        float var = s2 * (1.f / 16.f) - mu * mu;
        float ns  = 1.0f;
        if (nscale) {
            float nv = *nscale;
            if (isfinite(nv) && fabsf(nv) > 1e-6f && fabsf(nv) < 1e6f) ns = nv;
        }
        float zn  = (mm - mu) / sqrtf(var + 1e-5f) * ns;

        sz[tid]  = zn;
        g_z[tid] = zn;
    }
    __syncthreads();

    if (tid < 32) {
        float qv = bq[tid];
        #pragma unroll
        for (int j = 0; j < 32; j++) qv += Wq[tid * 32 + j] * sz[j];
        g_qs[tid] = qv * C_SCALE;
    }

    if (out_final) {
        if (out_elems == 16) {
            // expected output = Re(z): even interleaved lanes
            if (tid < 16) out_final[tid] = sz[2 * tid];
        } else {
            if (tid < 32 && tid < out_elems) out_final[tid] = sz[tid];
        }
    }
}

// ---------------------------------------------------------------------------
// Launch: size-class based input mapping, robust to insertion vs sorted order
// ---------------------------------------------------------------------------
extern "C" void kernel_launch(void* const* d_in, const int* in_sizes, int n_in,
                              void* d_out, int out_size)
{
    int idx32[8], n32 = 0;
    int idx1k[8], n1k = 0;
    int idx1[4],  n1  = 0;
    int idxRel = -1, idxCoup = -1, idxBig = -1;
    long long bigSize = 0;
    for (int i = 0; i < n_in; i++) {
        int s = in_sizes[i];
        if (s == 32) { if (n32 < 8) idx32[n32++] = i; }
        else if (s == 1024) { if (n1k < 8) idx1k[n1k++] = i; }
        else if (s == 4128) idxRel = i;
        else if (s == 8) idxCoup = i;
        else if (s == 1) { if (n1 < 4) idx1[n1++] = i; }
        else if ((long long)s > bigSize) { bigSize = s; idxBig = i; }
    }
    if (idxBig < 0 || idxRel < 0 || idxCoup < 0 || n32 < 5 || n1k < 4) return;

    const float* cand; const float* Wq; const float* bq;
    const float* Wk;   const float* bk;
    const float* Wv;   const float* bv;
    const float* Wo;   const float* bo;

    bool insertion = idx32[0] < idx1k[0];
    if (insertion) {
        cand = (const float*)d_in[idx32[0]];
        bq   = (const float*)d_in[idx32[1]];
        bk   = (const float*)d_in[idx32[2]];
        bv   = (const float*)d_in[idx32[3]];
        bo   = (const float*)d_in[idx32[4]];
        Wq   = (const float*)d_in[idx1k[0]];
        Wk   = (const float*)d_in[idx1k[1]];
        Wv   = (const float*)d_in[idx1k[2]];
        Wo   = (const float*)d_in[idx1k[3]];
    } else {
        Wk   = (const float*)d_in[idx1k[0]];
        Wo   = (const float*)d_in[idx1k[1]];
        Wq   = (const float*)d_in[idx1k[2]];
        Wv   = (const float*)d_in[idx1k[3]];
        bk   = (const float*)d_in[idx32[0]];
        bo   = (const float*)d_in[idx32[1]];
        bq   = (const float*)d_in[idx32[2]];
        bv   = (const float*)d_in[idx32[3]];
        cand = (const float*)d_in[idx32[4]];
    }
    const float* rel  = (const float*)d_in[idxRel];
    const float* coup = (const float*)d_in[idxCoup];
    const float* nsc  = (n1 > 0) ? (const float*)d_in[idx1[0]] : nullptr;
    const int*   pos  = (n1 > 1) ? (const int*)d_in[idx1[1]] : nullptr;

    int P = in_sizes[idxBig] / 32;
    if (P > P_MAX) P = P_MAX;
    int PAD = (P + 31) & ~31;

    int nprec = (PAD + 127) / 128;
    precompute_kernel<<<nprec, 128>>>((const float*)d_in[idxBig],
                                      Wk, bk, Wv, bv, rel, pos, P, PAD);
    init_kernel<<<1, 32>>>(cand, Wq, bq);

    int ntiles = PAD / 32;
    const int NB = 296;   // 2 blocks/SM on 148 SMs
    for (int m = 0; m < M_STEPS; m++) {
        step_kernel<<<NB, 256>>>(ntiles, P);
        finalize_kernel<<<1, 128>>>(Wo, bo, Wq, bq, coup, nsc, m, NB,
                                    (m == M_STEPS - 1) ? (float*)d_out : nullptr,
                                    out_size);
    }
}

// round 4
// speedup vs baseline: 2.1273x; 2.1273x over previous
#include <cuda_runtime.h>
#include <cuda_bf16.h>
#include <cstdint>

typedef unsigned long long ull;
typedef unsigned int u32;

#define M_STEPS 8
#define RMAX 64
#define P_MAX 524288
#define NB 296
// fold inv_sqrt(HD)=0.5 and log2(e) into q: hot loop = dot + EX2 only
#define C_SCALE (0.5f * 1.4426950408889634f)

// ---------------------------------------------------------------------------
// Scratch (device globals; no allocations allowed)
// g_kev: per tile of 32 positions, 8 uint4 per position (bf16), transposed:
//   g_kev[tile*256 + j*32 + lane] : chunk j of position (tile*32+lane)
//   j 0..3 = KE dims 8j..8j+7 (k + bk + rel, bf16), j 4..7 = V dims 8(j-4)..
// ---------------------------------------------------------------------------
__device__ uint4 g_kev[(size_t)(P_MAX / 32) * 256];   // 64 MB
__device__ float g_qs[32];
__device__ float g_z[32];
__device__ float g_partials[NB * 36];
__device__ int   g_tick[M_STEPS];

// ---------------------------------------------------------------------------
// small PTX helpers
// ---------------------------------------------------------------------------
__device__ __forceinline__ ull fma2(ull a, ull b, ull c) {
    ull d; asm("fma.rn.f32x2 %0, %1, %2, %3;" : "=l"(d) : "l"(a), "l"(b), "l"(c));
    return d;
}
__device__ __forceinline__ float2 unpack2(ull a) {
    float2 r; asm("mov.b64 {%0, %1}, %2;" : "=f"(r.x), "=f"(r.y) : "l"(a));
    return r;
}
__device__ __forceinline__ u32 hfma2bf(u32 a, u32 b, u32 c) {
    u32 d; asm("fma.rn.bf16x2 %0, %1, %2, %3;" : "=r"(d) : "r"(a), "r"(b), "r"(c));
    return d;
}
__device__ __forceinline__ u32 packbf2(float lo, float hi) {
    u32 d; asm("cvt.rn.bf16x2.f32 %0, %1, %2;" : "=r"(d) : "f"(hi), "f"(lo));
    return d;
}
__device__ __forceinline__ float bf_lo(u32 v) { return __uint_as_float(v << 16); }
__device__ __forceinline__ float bf_hi(u32 v) { return __uint_as_float(v & 0xFFFF0000u); }
__device__ __forceinline__ float ex2f(float x) {
    float y; asm("ex2.approx.ftz.f32 %0, %1;" : "=f"(y) : "f"(x)); return y;
}

// ---------------------------------------------------------------------------
// Precompute (FMA2, lane = output dim, W rows in registers):
//   KE[p] = Wk x_p + bk + rel[idx(p)],  V[p] = Wv x_p + bv   -> bf16, transposed
// ---------------------------------------------------------------------------
__global__ __launch_bounds__(256) void precompute_kernel(
    const float* __restrict__ z_past,
    const float* __restrict__ Wk, const float* __restrict__ bk,
    const float* __restrict__ Wv, const float* __restrict__ bv,
    const float* __restrict__ rel, const int* __restrict__ posp,
    int P, int ntiles)
{
    extern __shared__ char dyn[];
    float* srel = (float*)dyn;                          // 129*32 f = 16512 B (rel + bk)
    float* sx   = (float*)(dyn + 16512);                // 8 warps * 1024 f = 32768 B
    uint4* sstg = (uint4*)(dyn + 16512 + 32768);        // 8 warps * 288 u4 = 36864 B

    int tid = threadIdx.x, wid = tid >> 5, lane = tid & 31;

    for (int i = tid; i < 129 * 32; i += 256) srel[i] = rel[i] + bk[i & 31];
    __syncthreads();

    // per-lane W rows as f32x2 pairs (lane = output dim)
    ull wk2[16], wv2[16];
    const ull* Wkp = (const ull*)Wk;
    const ull* Wvp = (const ull*)Wv;
    #pragma unroll
    for (int j = 0; j < 16; j++) { wk2[j] = Wkp[lane * 16 + j]; wv2[j] = Wvp[lane * 16 + j]; }
    float bvl = bv[lane];

    // robust pos decode
    int pos = P;
    if (posp) {
        int v = *posp;
        if (v > 0 && v < (1 << 28)) pos = v;
        else { float fv = __int_as_float(v); if (fv > 0.f && fv < 2.68e8f) pos = (int)fv; }
    }
    int dpos = pos - P + RMAX;

    float* mysx = sx + wid * 1024;
    uint4* myst = sstg + wid * 288;                      // row pitch 9 u4 (144 B)
    unsigned short* myst16 = (unsigned short*)myst;      // row pitch 72 ushort

    int gw = blockIdx.x * 8 + wid, nw = gridDim.x * 8;
    for (int t = gw; t < ntiles; t += nw) {
        // stage x tile (32 pos x 32 f), zero-filled past P
        const float4* src = (const float4*)z_past + (size_t)t * 256;
        float4* dst = (float4*)mysx;
        int vcnt = P - t * 32;
        #pragma unroll
        for (int j = 0; j < 8; j++) {
            int fi = j * 32 + lane;
            float4 val = make_float4(0.f, 0.f, 0.f, 0.f);
            if ((fi >> 3) < vcnt) val = src[fi];
            dst[fi] = val;
        }
        __syncwarp();

        #pragma unroll 1
        for (int p = 0; p < 32; p++) {
            const ull* x2 = (const ull*)mysx + p * 16;   // broadcast reads
            ull ak = 0ull, av = 0ull;
            #pragma unroll
            for (int j = 0; j < 16; j++) {
                ull xx = x2[j];
                ak = fma2(wk2[j], xx, ak);
                av = fma2(wv2[j], xx, av);
            }
            float2 fk = unpack2(ak), fv2 = unpack2(av);
            int gp = t * 32 + p;
            int idx = gp + dpos; idx = min(max(idx, 0), 2 * RMAX);
            float kk = fk.x + fk.y + srel[idx * 32 + lane];
            float vv = fv2.x + fv2.y + bvl;
            if (gp >= P) { kk = 0.f; vv = 0.f; }
            myst16[p * 72 + lane]      = __bfloat16_as_ushort(__float2bfloat16(kk));
            myst16[p * 72 + 32 + lane] = __bfloat16_as_ushort(__float2bfloat16(vv));
        }
        __syncwarp();

        // coalesced write-out: lane = position, 8 chunks
        uint4* out = g_kev + (size_t)t * 256;
        #pragma unroll
        for (int j = 0; j < 8; j++) out[j * 32 + lane] = myst[lane * 9 + j];
        __syncwarp();
    }
}

// ---------------------------------------------------------------------------
// Init: z = candidate, q0 = (Wq z + bq) * C_SCALE, zero tickets
// ---------------------------------------------------------------------------
__global__ void init_kernel(const float* __restrict__ cand,
                            const float* __restrict__ Wq,
                            const float* __restrict__ bq)
{
    __shared__ float sz[32];
    int i = threadIdx.x;   // 32 threads
    sz[i] = cand[i];
    __syncwarp();
    float q = bq[i];
    #pragma unroll
    for (int j = 0; j < 32; j++) q += Wq[i * 32 + j] * sz[j];
    g_z[i]  = sz[i];
    g_qs[i] = q * C_SCALE;
    if (i < M_STEPS) g_tick[i] = 0;
}

// ---------------------------------------------------------------------------
// Step: stream bf16 KEV, HFMA2 scores + V-acc, fp32 denominators.
// Last block (ticket election) reduces partials and runs the finalize chain.
// ---------------------------------------------------------------------------
__global__ __launch_bounds__(256, 2) void step_kernel(
    int ntiles, int P, int m,
    const float* __restrict__ Wo, const float* __restrict__ bo,
    const float* __restrict__ Wq, const float* __restrict__ bq,
    const float* __restrict__ coupling, const float* __restrict__ nscale,
    float* __restrict__ out_final, int out_elems)
{
    __shared__ float sq[32];
    __shared__ float sred[8][36];
    __shared__ int   sIsLast;
    __shared__ float sgrp[7][36];
    __shared__ float red[36];
    __shared__ float sout[32], sz[32];

    if (threadIdx.x < 32) sq[threadIdx.x] = g_qs[threadIdx.x];
    __syncthreads();

    u32 q2[16];
    #pragma unroll
    for (int j = 0; j < 16; j++) q2[j] = packbf2(sq[2 * j], sq[2 * j + 1]);

    u32 accv[16];
    #pragma unroll
    for (int j = 0; j < 16; j++) accv[j] = 0u;
    float l[4] = {0.f, 0.f, 0.f, 0.f};

    int lane = threadIdx.x & 31;
    int gw   = (blockIdx.x * blockDim.x + threadIdx.x) >> 5;
    int nw   = (gridDim.x * blockDim.x) >> 5;

    for (int t = gw; t < ntiles; t += nw) {
        const uint4* b = g_kev + (size_t)t * 256 + lane;
        uint4 ke[4];
        #pragma unroll
        for (int j = 0; j < 4; j++) ke[j] = b[j * 32];

        float mask = (t * 32 + lane < P) ? 1.f : 0.f;
        float w[4];
        #pragma unroll
        for (int h = 0; h < 4; h++) {
            u32 a = 0u;
            a = hfma2bf(ke[h].x, q2[4 * h + 0], a);
            a = hfma2bf(ke[h].y, q2[4 * h + 1], a);
            a = hfma2bf(ke[h].z, q2[4 * h + 2], a);
            a = hfma2bf(ke[h].w, q2[4 * h + 3], a);
            float s = bf_lo(a) + bf_hi(a);
            w[h] = ex2f(s) * mask;
            l[h] += w[h];
        }
        #pragma unroll
        for (int h = 0; h < 4; h++) {
            uint4 v = b[(4 + h) * 32];
            u32 w2 = packbf2(w[h], w[h]);
            accv[4 * h + 0] = hfma2bf(v.x, w2, accv[4 * h + 0]);
            accv[4 * h + 1] = hfma2bf(v.y, w2, accv[4 * h + 1]);
            accv[4 * h + 2] = hfma2bf(v.z, w2, accv[4 * h + 2]);
            accv[4 * h + 3] = hfma2bf(v.w, w2, accv[4 * h + 3]);
        }
    }

    // 36-value reduction: warp, then block, then per-block partial
    float vals[36];
    #pragma unroll
    for (int j = 0; j < 16; j++) { vals[2 * j] = bf_lo(accv[j]); vals[2 * j + 1] = bf_hi(accv[j]); }
    #pragma unroll
    for (int h = 0; h < 4; h++) vals[32 + h] = l[h];

    #pragma unroll
    for (int off = 16; off; off >>= 1) {
        #pragma unroll
        for (int k = 0; k < 36; k++)
            vals[k] += __shfl_xor_sync(0xffffffffu, vals[k], off);
    }
    int warp = threadIdx.x >> 5;
    if (lane == 0) {
        #pragma unroll
        for (int k = 0; k < 36; k++) sred[warp][k] = vals[k];
    }
    __syncthreads();
    if (threadIdx.x < 36) {
        float ssum = 0.f;
        #pragma unroll
        for (int wb = 0; wb < 8; wb++) ssum += sred[wb][threadIdx.x];
        g_partials[blockIdx.x * 36 + threadIdx.x] = ssum;
    }

    // ticket election: last finishing block does the finalize chain
    __threadfence();
    if (threadIdx.x == 0) {
        int prev = atomicAdd(&g_tick[m], 1);
        sIsLast = (prev == (int)gridDim.x - 1);
    }
    __syncthreads();
    if (!sIsLast) return;

    int tid = threadIdx.x;
    int nblocks = gridDim.x;
    int chunk = (nblocks + 6) / 7;
    if (tid < 252) {
        int g = tid / 36, k = tid % 36;
        int b0 = g * chunk, b1 = min(b0 + chunk, nblocks);
        float s = 0.f;
        for (int b = b0; b < b1; b++) s += __ldcg(&g_partials[b * 36 + k]);
        sgrp[g][k] = s;
    }
    __syncthreads();
    if (tid < 36) {
        float s = 0.f;
        #pragma unroll
        for (int g = 0; g < 7; g++) s += sgrp[g][tid];
        red[tid] = s;
    }
    __syncthreads();
    if (tid < 32) sout[tid] = red[tid] / red[32 + (tid >> 3)];
    __syncthreads();

    if (tid < 32) {
        float mod = bo[tid];
        #pragma unroll
        for (int j = 0; j < 32; j++) mod += Wo[tid * 32 + j] * sout[j];
        float zz = g_z[tid] + coupling[m] * mod;

        // mish(x) = x * tanh(softplus(x)), elementwise on re & im
        float sp = (zz > 20.f) ? zz : log1pf(expf(zz));
        float mm = zz * tanhf(sp);

        // LayerNorm over even (real) / odd (imag) parity classes
        float s1 = mm, s2 = mm * mm;
        #pragma unroll
        for (int off = 2; off < 32; off <<= 1) {
            s1 += __shfl_xor_sync(0xffffffffu, s1, off);
            s2 += __shfl_xor_sync(0xffffffffu, s2, off);
        }
        float mu  = s1 * (1.f / 16.f);
        float var = s2 * (1.f / 16.f) - mu * mu;
        float ns  = 1.0f;
        if (nscale) {
            float nv = *nscale;
            if (isfinite(nv) && fabsf(nv) > 1e-6f && fabsf(nv) < 1e6f) ns = nv;
        }
        float zn = (mm - mu) / sqrtf(var + 1e-5f) * ns;

        sz[tid]  = zn;
        g_z[tid] = zn;
    }
    __syncwarp(0xffffffffu);
    if (tid < 32) {
        float qv = bq[tid];
        #pragma unroll
        for (int j = 0; j < 32; j++) qv += Wq[tid * 32 + j] * sz[j];
        g_qs[tid] = qv * C_SCALE;
    }
    if (out_final && tid < 16) {
        if (out_elems == 16) out_final[tid] = sz[2 * tid];           // Re(z)
        else { out_final[2 * tid] = sz[2 * tid]; if (2 * tid + 1 < out_elems) out_final[2 * tid + 1] = sz[2 * tid + 1]; }
    }
}

// ---------------------------------------------------------------------------
// Launch: size-class based input mapping (validated in R3)
// ---------------------------------------------------------------------------
extern "C" void kernel_launch(void* const* d_in, const int* in_sizes, int n_in,
                              void* d_out, int out_size)
{
    int idx32[8], n32 = 0;
    int idx1k[8], n1k = 0;
    int idx1[4],  n1  = 0;
    int idxRel = -1, idxCoup = -1, idxBig = -1;
    long long bigSize = 0;
    for (int i = 0; i < n_in; i++) {
        int s = in_sizes[i];
        if (s == 32) { if (n32 < 8) idx32[n32++] = i; }
        else if (s == 1024) { if (n1k < 8) idx1k[n1k++] = i; }
        else if (s == 4128) idxRel = i;
        else if (s == 8) idxCoup = i;
        else if (s == 1) { if (n1 < 4) idx1[n1++] = i; }
        else if ((long long)s > bigSize) { bigSize = s; idxBig = i; }
    }
    if (idxBig < 0 || idxRel < 0 || idxCoup < 0 || n32 < 5 || n1k < 4) return;

    const float *cand, *Wq, *bq, *Wk, *bk, *Wv, *bv, *Wo, *bo;
    bool insertion = idx32[0] < idx1k[0];
    if (insertion) {
        cand = (const float*)d_in[idx32[0]];
        bq   = (const float*)d_in[idx32[1]];
        bk   = (const float*)d_in[idx32[2]];
        bv   = (const float*)d_in[idx32[3]];
        bo   = (const float*)d_in[idx32[4]];
        Wq   = (const float*)d_in[idx1k[0]];
        Wk   = (const float*)d_in[idx1k[1]];
        Wv   = (const float*)d_in[idx1k[2]];
        Wo   = (const float*)d_in[idx1k[3]];
    } else {
        Wk   = (const float*)d_in[idx1k[0]];
        Wo   = (const float*)d_in[idx1k[1]];
        Wq   = (const float*)d_in[idx1k[2]];
        Wv   = (const float*)d_in[idx1k[3]];
        bk   = (const float*)d_in[idx32[0]];
        bo   = (const float*)d_in[idx32[1]];
        bq   = (const float*)d_in[idx32[2]];
        bv   = (const float*)d_in[idx32[3]];
        cand = (const float*)d_in[idx32[4]];
    }
    const float* rel  = (const float*)d_in[idxRel];
    const float* coup = (const float*)d_in[idxCoup];
    const float* nsc  = (n1 > 0) ? (const float*)d_in[idx1[0]] : nullptr;
    const int*   pos  = (n1 > 1) ? (const int*)d_in[idx1[1]] : nullptr;

    int P = in_sizes[idxBig] / 32;
    if (P > P_MAX) P = P_MAX;
    int PAD = (P + 31) & ~31;
    int ntiles = PAD / 32;

    static int smem_set = 0;
    const int PRE_SMEM = 16512 + 32768 + 36864;   // 86144 B
    if (!smem_set) {
        cudaFuncSetAttribute(precompute_kernel,
                             cudaFuncAttributeMaxDynamicSharedMemorySize, PRE_SMEM);
        smem_set = 1;
    }

    precompute_kernel<<<148, 256, PRE_SMEM>>>((const float*)d_in[idxBig],
                                              Wk, bk, Wv, bv, rel, pos, P, ntiles);
    init_kernel<<<1, 32>>>(cand, Wq, bq);

    for (int m = 0; m < M_STEPS; m++) {
        step_kernel<<<NB, 256>>>(ntiles, P, m, Wo, bo, Wq, bq, coup, nsc,
                                 (m == M_STEPS - 1) ? (float*)d_out : nullptr,
                                 out_size);
    }
}